// round 16
// baseline (speedup 1.0000x reference)
#include <cuda_runtime.h>
#include <cuda_fp16.h>
#include <math.h>
#include <cstdint>

#define N_ROWS 8192
#define K_DIM  512
#define F_DIM  256
#define NCHUNK 512
#define CHUNK  16

// ---------------- scratch (device globals) ----------------
__device__ __half g_wt[F_DIM * K_DIM];           // W^T fp16  [256][512]
__device__ float g_h[N_ROWS * F_DIM];
__device__ float g_f[N_ROWS];
__device__ float g_g[N_ROWS];
__device__ float g_gs[N_ROWS];
__device__ int   g_gidx[N_ROWS];
__device__ int   g_rank[N_ROWS];
__device__ int   g_cnt[N_ROWS];
__device__ float g_loc[(size_t)(N_ROWS + 1) * 512];
__device__ float g_choff[(size_t)(NCHUNK + 1) * 512];
__device__ float g_aggH[NCHUNK * F_DIM];
__device__ float g_aggE[NCHUNK * F_DIM];
__device__ float g_aggW[NCHUNK];
__device__ float g_lsufW[N_ROWS + 1];
__device__ float g_choffW[NCHUNK + 1];

// ---------------- helpers ----------------
__device__ __forceinline__ uint32_t smem_u32(const void* p) {
    uint32_t a;
    asm("{ .reg .u64 t; cvta.to.shared.u64 t, %1; cvt.u32.u64 %0, t; }" : "=r"(a) : "l"(p));
    return a;
}
__device__ __forceinline__ void ldsm_x4(uint32_t (&r)[4], uint32_t addr) {
    asm volatile("ldmatrix.sync.aligned.m8n8.x4.shared.b16 {%0,%1,%2,%3}, [%4];"
                 : "=r"(r[0]), "=r"(r[1]), "=r"(r[2]), "=r"(r[3]) : "r"(addr));
}
__device__ __forceinline__ void mma16816(float (&d)[4], const uint32_t (&a)[4],
                                         uint32_t b0, uint32_t b1) {
    asm volatile(
        "mma.sync.aligned.m16n8k16.row.col.f32.f16.f16.f32 "
        "{%0,%1,%2,%3}, {%4,%5,%6,%7}, {%8,%9}, {%0,%1,%2,%3};"
        : "+f"(d[0]), "+f"(d[1]), "+f"(d[2]), "+f"(d[3])
        : "r"(a[0]), "r"(a[1]), "r"(a[2]), "r"(a[3]), "r"(b0), "r"(b1));
}
__device__ __forceinline__ void cp16(uint32_t dst, const void* src) {
    asm volatile("cp.async.cg.shared.global [%0], [%1], 16;" :: "r"(dst), "l"(src));
}
__device__ __forceinline__ uint32_t f2h2(float a, float b) {
    __half2 t(__float2half_rn(a), __float2half_rn(b));
    return *reinterpret_cast<uint32_t*>(&t);
}

// ---------------- 0) W convert + transpose + zero-inits (small) ----------------
#define WBLOCKS (K_DIM * F_DIM / 256)     // 512
__global__ void wconvert_kernel(const float* __restrict__ W) {
    const int idx = blockIdx.x * 256 + threadIdx.x;  // 0..131071
    if (idx < N_ROWS) {
        g_rank[idx] = 0; g_cnt[idx] = 0;
        g_f[idx] = 0.f;  g_g[idx] = 0.f;
    }
    const int k = idx >> 8;
    const int n = idx & 255;
    g_wt[(size_t)n * K_DIM + k] = __float2half_rn(W[idx]);
}

// ---------------- 1) GEMM: h = fp16(x) @ fp16(W), fp32 accumulate ----------------
// CTA tile 128x128, K-chunk 64, 256 threads (8 warps 2x4).
// SMEM/buffer: AH(128x72 fp16) BH = 2*18432 = 36864.
#define GSTRIDE 72
#define TILE_B  18432
#define BUFSZ   36864
#define SM_A1A2 (2 * BUFSZ)

__device__ __forceinline__ void load_x_regs(float4 (&xv)[8], const float* __restrict__ x,
                                            int bm, int k0, int tid) {
    #pragma unroll
    for (int l = 0; l < 8; l++) {
        int idx = tid + l * 256;
        int r = idx >> 4, c4 = idx & 15;
        xv[l] = *(const float4*)(x + (size_t)(bm + r) * K_DIM + k0 + c4 * 4);
    }
}
__device__ __forceinline__ void sts_x(uint32_t sb, int buf, const float4 (&xv)[8], int tid) {
    uint32_t base = sb + buf * BUFSZ;
    #pragma unroll
    for (int l = 0; l < 8; l++) {
        int idx = tid + l * 256;
        int r = idx >> 4, c4 = idx & 15;
        uint32_t off = (uint32_t)(r * GSTRIDE + c4 * 4) * 2;
        float4 v = xv[l];
        uint32_t hi0 = f2h2(v.x, v.y), hi1 = f2h2(v.z, v.w);
        asm volatile("st.shared.v2.b32 [%0], {%1, %2};"
                     :: "r"(base + off), "r"(hi0), "r"(hi1));
    }
}
__device__ __forceinline__ void cp_w(uint32_t sb, int buf, int k0, int bn, int tid) {
    uint32_t base = sb + buf * BUFSZ;
    #pragma unroll
    for (int l = 0; l < 4; l++) {
        int idx = tid + l * 256;
        int r = idx >> 3, c8 = (idx & 7) * 8;
        uint32_t off = (uint32_t)(r * GSTRIDE + c8) * 2;
        cp16(base + TILE_B + off, g_wt + (size_t)(bn + r) * K_DIM + k0 + c8);
    }
}

__global__ void __launch_bounds__(256, 1) gemm_mma_kernel(const float* __restrict__ x,
                                                          const float* __restrict__ a) {
    extern __shared__ char smem[];
    const uint32_t sb = smem_u32(smem);
    float* sa = (float*)(smem + SM_A1A2);
    const int tid = threadIdx.x;
    const int wid = tid >> 5, lane = tid & 31;
    const int warp_m = wid >> 2;
    const int warp_n = wid & 3;
    const int bm = blockIdx.y * 128;
    const int bn = blockIdx.x * 128;

    float acc[4][4][4];
    #pragma unroll
    for (int mt = 0; mt < 4; mt++)
        #pragma unroll
        for (int nt = 0; nt < 4; nt++)
            #pragma unroll
            for (int r = 0; r < 4; r++) acc[mt][nt][r] = 0.f;

    const int a_row = warp_m * 64 + (lane & 15);
    const int a_col = (lane >> 4) * 8;
    const int b_row = warp_n * 32 + ((lane >> 4) & 1) * 8 + (lane & 7);
    const int b_col = ((lane >> 3) & 1) * 8;

    sa[tid] = a[tid];
    sa[256 + tid] = a[256 + tid];

    float4 xv[8];
    load_x_regs(xv, x, bm, 0, tid);
    cp_w(sb, 0, 0, bn, tid);
    asm volatile("cp.async.commit_group;" ::: "memory");

    for (int i = 0; i < 8; i++) {
        asm volatile("cp.async.wait_group 0;" ::: "memory");
        __syncthreads();                  // W[i] visible; prev-iter MMA done
        const int b = i & 1;
        sts_x(sb, b, xv, tid);            // x[i] fp16 into smem
        if (i < 7) {
            load_x_regs(xv, x, bm, (i + 1) * 64, tid);   // overlaps MMA below
            cp_w(sb, b ^ 1, (i + 1) * 64, bn, tid);
            asm volatile("cp.async.commit_group;" ::: "memory");
        }
        __syncthreads();                  // x tile visible to all warps
        const uint32_t bufb = sb + b * BUFSZ;
        #pragma unroll
        for (int kk = 0; kk < 4; kk++) {
            uint32_t ah[4][4], bh[2][4];
            #pragma unroll
            for (int mt = 0; mt < 4; mt++) {
                uint32_t off = (uint32_t)((a_row + mt * 16) * GSTRIDE + kk * 16 + a_col) * 2;
                ldsm_x4(ah[mt], bufb + off);
            }
            #pragma unroll
            for (int np = 0; np < 2; np++) {
                uint32_t off = (uint32_t)((b_row + np * 16) * GSTRIDE + kk * 16 + b_col) * 2;
                ldsm_x4(bh[np], bufb + TILE_B + off);
            }
            #pragma unroll
            for (int mt = 0; mt < 4; mt++) {
                #pragma unroll
                for (int nt = 0; nt < 4; nt++) {
                    int np = nt >> 1, p = (nt & 1) * 2;
                    mma16816(acc[mt][nt], ah[mt], bh[np][p], bh[np][p + 1]);
                }
            }
        }
        __syncthreads();
    }

    // epilogue: write h + fused f/g partial dot products
    const int g = lane >> 2, t = lane & 3;
    #pragma unroll
    for (int mt = 0; mt < 4; mt++) {
        const int row = bm + warp_m * 64 + mt * 16 + g;
        float f0 = 0.f, g0 = 0.f, f1 = 0.f, g1 = 0.f;
        #pragma unroll
        for (int nt = 0; nt < 4; nt++) {
            const int colS = bn + warp_n * 32 + nt * 8 + t * 2;
            const float a1c0 = sa[colS],       a1c1 = sa[colS + 1];
            const float a2c0 = sa[256 + colS], a2c1 = sa[256 + colS + 1];
            *(float2*)(g_h + (size_t)row * F_DIM + colS) =
                make_float2(acc[mt][nt][0], acc[mt][nt][1]);
            *(float2*)(g_h + (size_t)(row + 8) * F_DIM + colS) =
                make_float2(acc[mt][nt][2], acc[mt][nt][3]);
            f0 += acc[mt][nt][0] * a1c0 + acc[mt][nt][1] * a1c1;
            g0 += acc[mt][nt][0] * a2c0 + acc[mt][nt][1] * a2c1;
            f1 += acc[mt][nt][2] * a1c0 + acc[mt][nt][3] * a1c1;
            g1 += acc[mt][nt][2] * a2c0 + acc[mt][nt][3] * a2c1;
        }
        #pragma unroll
        for (int o = 1; o < 4; o <<= 1) {
            f0 += __shfl_xor_sync(0xffffffffu, f0, o);
            g0 += __shfl_xor_sync(0xffffffffu, g0, o);
            f1 += __shfl_xor_sync(0xffffffffu, f1, o);
            g1 += __shfl_xor_sync(0xffffffffu, g1, o);
        }
        if (t == 0) {
            atomicAdd(g_f + row, f0);
            atomicAdd(g_g + row, g0);
            atomicAdd(g_f + row + 8, f1);
            atomicAdd(g_g + row + 8, g1);
        }
    }
}

// ---------------- 2) rank-sort + inline scatter ----------------
__global__ void rank_kernel() {
    __shared__ float sj[1024];
    const int tid = threadIdx.x;
    const int bi = blockIdx.x;          // 32
    const int bj = blockIdx.y;          // 8
    const int jbase = bj * 1024;
    *(float4*)&sj[tid * 4] = *(const float4*)(g_g + jbase + tid * 4);
    __syncthreads();
    const int i = bi * 256 + tid;
    const float vi = g_g[i];
    int cnt = 0;
    #pragma unroll 4
    for (int jj = 0; jj < 1024; jj += 4) {
        float4 v = *(const float4*)&sj[jj];
        int j0 = jbase + jj;
        cnt += (v.x < vi) || (v.x == vi && (j0 + 0) < i);
        cnt += (v.y < vi) || (v.y == vi && (j0 + 1) < i);
        cnt += (v.z < vi) || (v.z == vi && (j0 + 2) < i);
        cnt += (v.w < vi) || (v.w == vi && (j0 + 3) < i);
    }
    atomicAdd(&g_rank[i], cnt);
    __threadfence();
    if (atomicAdd(&g_cnt[i], 1) == 7) {
        int r = atomicAdd(&g_rank[i], 0);
        g_gs[r] = vi;
        g_gidx[r] = i;
    }
}

// ---------------- 3) scan A ----------------
__global__ void scanA_kernel() {
    __shared__ int   sidx[CHUNK];
    __shared__ float sw[CHUNK];
    const int blk = blockIdx.x;
    const int c = threadIdx.x;
    const int base = blk * CHUNK;
    if (c < CHUNK) {
        sidx[c] = g_gidx[base + c];
        sw[c] = expf(g_gs[base + c] - g_gs[N_ROWS - 1]);
    }
    __syncthreads();
    float hv[CHUNK];
    #pragma unroll
    for (int r = 0; r < CHUNK; r++)
        hv[r] = g_h[(size_t)sidx[r] * F_DIM + c];
    float run = 0.f;
    #pragma unroll
    for (int r = 0; r < CHUNK; r++) {
        g_loc[(size_t)(base + r) * 512 + c] = run;
        run += hv[r];
    }
    g_aggH[blk * F_DIM + c] = run;
    float runE = 0.f;
    #pragma unroll
    for (int r = CHUNK - 1; r >= 0; r--) {
        runE += sw[r] * hv[r];
        g_loc[(size_t)(base + r) * 512 + 256 + c] = runE;
    }
    g_aggE[blk * F_DIM + c] = runE;
    if (c == 0) {
        float runW = 0.f;
        #pragma unroll
        for (int r = CHUNK - 1; r >= 0; r--) {
            runW += sw[r];
            g_lsufW[base + r] = runW;
        }
        g_aggW[blk] = runW;
    }
}

// ---------------- 4) scan B ----------------
__global__ void scanB_kernel() {
    const unsigned FULL = 0xffffffffu;
    const int warp = threadIdx.x >> 5, lane = threadIdx.x & 31;
    const int c = blockIdx.x * 8 + warp;
    float carry = 0.f;
    for (int s = 0; s < NCHUNK; s += 32) {
        float v = g_aggH[(s + lane) * F_DIM + c];
        float x = v;
        #pragma unroll
        for (int o = 1; o < 32; o <<= 1) {
            float t = __shfl_up_sync(FULL, x, o);
            if (lane >= o) x += t;
        }
        g_choff[(size_t)(s + lane) * 512 + c] = carry + x - v;
        carry += __shfl_sync(FULL, x, 31);
    }
    float carryE = 0.f;
    for (int s = NCHUNK - 32; s >= 0; s -= 32) {
        float v = g_aggE[(s + lane) * F_DIM + c];
        float x = v;
        #pragma unroll
        for (int o = 1; o < 32; o <<= 1) {
            float t = __shfl_down_sync(FULL, x, o);
            if (lane + o < 32) x += t;
        }
        g_choff[(size_t)(s + lane) * 512 + 256 + c] = carryE + x - v;
        carryE += __shfl_sync(FULL, x, 0);
    }
    if (lane == 0) {
        g_choff[(size_t)NCHUNK * 512 + c] = carry;
        g_choff[(size_t)NCHUNK * 512 + 256 + c] = 0.f;
        g_loc[(size_t)N_ROWS * 512 + c] = 0.f;
        g_loc[(size_t)N_ROWS * 512 + 256 + c] = 0.f;
    }
    if (blockIdx.x == 0 && warp == 0) {
        float cw = 0.f;
        for (int s = NCHUNK - 32; s >= 0; s -= 32) {
            float v = g_aggW[s + lane];
            float x = v;
            #pragma unroll
            for (int o = 1; o < 32; o <<= 1) {
                float t = __shfl_down_sync(FULL, x, o);
                if (lane + o < 32) x += t;
            }
            g_choffW[s + lane] = cw + x - v;
            cw += __shfl_sync(FULL, x, 0);
        }
        if (lane == 0) { g_choffW[NCHUNK] = 0.f; g_lsufW[N_ROWS] = 0.f; }
    }
}

// ---------------- 5) output ----------------
__global__ void out_kernel(float* __restrict__ out) {
    const int warp = threadIdx.x >> 5, lane = threadIdx.x & 31;
    const int i = blockIdx.x * 8 + warp;
    int k; float alpha, beta, inv;
    if (lane == 0) {
        float fi = g_f[i];
        float gmax = g_gs[N_ROWS - 1];
        float t = fi + gmax;
        float thr = -fi;
        int lo = 0, hi = N_ROWS;
        while (lo < hi) {
            int mid = (lo + hi) >> 1;
            if (g_gs[mid] <= thr) lo = mid + 1; else hi = mid;
        }
        k = lo;
        alpha = expf(fminf(t, 0.f));
        beta  = expf(-fmaxf(t, 0.f));
        float sufWk = g_choffW[k >> 4] + g_lsufW[k];
        inv = 1.f / (alpha * sufWk + beta * (float)k);
    }
    k     = __shfl_sync(0xffffffffu, k, 0);
    alpha = __shfl_sync(0xffffffffu, alpha, 0);
    beta  = __shfl_sync(0xffffffffu, beta, 0);
    inv   = __shfl_sync(0xffffffffu, inv, 0);
    const float* loc = g_loc   + (size_t)k * 512;
    const float* cof = g_choff + (size_t)(k >> 4) * 512;
    float4* po = (float4*)(out + (size_t)i * F_DIM);
    #pragma unroll
    for (int j = 0; j < 2; j++) {
        int idx = lane + 32 * j;
        float4 lh = ((const float4*)loc)[idx];
        float4 le = ((const float4*)(loc + 256))[idx];
        float4 ch = ((const float4*)cof)[idx];
        float4 ce = ((const float4*)(cof + 256))[idx];
        float4 y;
        y.x = (alpha * (ce.x + le.x) + beta * (ch.x + lh.x)) * inv;
        y.y = (alpha * (ce.y + le.y) + beta * (ch.y + lh.y)) * inv;
        y.z = (alpha * (ce.z + le.z) + beta * (ch.z + lh.z)) * inv;
        y.w = (alpha * (ce.w + le.w) + beta * (ch.w + lh.w)) * inv;
        y.x = (y.x > 0.f) ? y.x : expm1f(y.x);
        y.y = (y.y > 0.f) ? y.y : expm1f(y.y);
        y.z = (y.z > 0.f) ? y.z : expm1f(y.z);
        y.w = (y.w > 0.f) ? y.w : expm1f(y.w);
        po[idx] = y;
    }
}

// ---------------- launch ----------------
extern "C" void kernel_launch(void* const* d_in, const int* in_sizes, int n_in,
                              void* d_out, int out_size) {
    const float* x = (const float*)d_in[0];
    const float* W = (const float*)d_in[1];
    const float* a = (const float*)d_in[2];
    float* out = (float*)d_out;

    wconvert_kernel<<<WBLOCKS, 256>>>(W);

    cudaFuncSetAttribute(gemm_mma_kernel,
                         cudaFuncAttributeMaxDynamicSharedMemorySize, 2 * BUFSZ + 2048);
    gemm_mma_kernel<<<dim3(F_DIM / 128, N_ROWS / 128), 256, 2 * BUFSZ + 2048>>>(x, a);

    rank_kernel<<<dim3(N_ROWS / 256, 8), 256>>>();
    scanA_kernel<<<NCHUNK, F_DIM>>>();
    scanB_kernel<<<32, 256>>>();
    out_kernel<<<N_ROWS / 8, 256>>>(out);
}